// round 11
// baseline (speedup 1.0000x reference)
#include <cuda_runtime.h>
#include <cuda_fp16.h>
#include <math.h>
#include <stdint.h>

#define Bb 8
#define Nn 2048
#define Ff 64
#define MTILE 64
#define JT 64
#define NSTEPS (Nn / JT)        // 32

typedef unsigned long long ull;

// Scratch (device globals)
__device__ __half g_WhT[Bb * Ff * Nn];    // 2 MB f16  [b][f][j]
__device__ float4 g_e1pack[Bb * Nn];      // (e1, exp(e1), exp(0.2 e1), 0)
__device__ float4 g_e2pack[Bb * Nn];      // (e2, exp(e2), exp(0.2 e2), 0)
__device__ ull    g_adjmask[Nn * (Nn / 64)];   // 512 KB bitmask

// ------------------------- helpers ----------------------------
__device__ __forceinline__ uint32_t smem_u32(const void* p) {
    uint32_t a;
    asm("{ .reg .u64 t; cvta.to.shared.u64 t, %1; cvt.u32.u64 %0, t; }" : "=r"(a) : "l"(p));
    return a;
}
__device__ __forceinline__ uint32_t swz128(uint32_t off) {
    return off ^ ((off >> 3) & 0x70);
}
__device__ __forceinline__ void cp16(uint32_t dst, const void* src) {
    asm volatile("cp.async.cg.shared.global [%0], [%1], 16;" :: "r"(dst), "l"(src));
}
#define CP_COMMIT() asm volatile("cp.async.commit_group;" ::: "memory")
#define CP_WAIT0()  asm volatile("cp.async.wait_group 0;" ::: "memory")
__device__ __forceinline__ void ldsm_x4(uint32_t& r0, uint32_t& r1, uint32_t& r2, uint32_t& r3,
                                        uint32_t addr) {
    asm volatile("ldmatrix.sync.aligned.m8n8.x4.shared.b16 {%0,%1,%2,%3}, [%4];"
                 : "=r"(r0), "=r"(r1), "=r"(r2), "=r"(r3) : "r"(addr));
}
__device__ __forceinline__ void ldsm_x2(uint32_t& r0, uint32_t& r1, uint32_t addr) {
    asm volatile("ldmatrix.sync.aligned.m8n8.x2.shared.b16 {%0,%1}, [%2];"
                 : "=r"(r0), "=r"(r1) : "r"(addr));
}
__device__ __forceinline__ void mma16816(float* c, const uint32_t* a, const uint32_t* bf) {
    asm volatile(
        "mma.sync.aligned.m16n8k16.row.col.f32.f16.f16.f32 "
        "{%0,%1,%2,%3}, {%4,%5,%6,%7}, {%8,%9}, {%0,%1,%2,%3};"
        : "+f"(c[0]), "+f"(c[1]), "+f"(c[2]), "+f"(c[3])
        : "r"(a[0]), "r"(a[1]), "r"(a[2]), "r"(a[3]), "r"(bf[0]), "r"(bf[1]));
}

// ---------------------------------------------------------------------------
// Kernel 1: Wh = h @ W^T -> WhT f16 (fused transpose) + e1/e2 exp packs.
// 512 CTAs x 256 thr; 32 rows/CTA; thread = 2 rows x 4 outs.
// f-loop batched x4 (8 LDS then 32 FMA) with h transposed in smem.
// ---------------------------------------------------------------------------
__global__ __launch_bounds__(256) void prep_kernel(const float* __restrict__ h,
                                                   const float* __restrict__ W,
                                                   const float* __restrict__ a)
{
    __shared__ __align__(16) float W_s[64][64];    // [f][o]
    __shared__ float h_sT[64][34];                 // [f][r], stride 34
    __shared__ float red1[32][16];
    __shared__ float red2[32][16];
    __shared__ __align__(16) __half tT[64][40];    // [o][r]

    const int t = threadIdx.x;
    const int row0 = blockIdx.x * 32;

    for (int idx = t; idx < 64 * 64; idx += 256) {
        int o = idx >> 6, f = idx & 63;
        W_s[f][o] = W[idx];                        // W is [o][f]
    }
    {
        const float4* hg = (const float4*)(h + (size_t)row0 * 64);
        float4 v = hg[t];
        int r = t >> 4, c0 = (t & 15) * 4;
        h_sT[c0 + 0][r] = v.x; h_sT[c0 + 1][r] = v.y;
        h_sT[c0 + 2][r] = v.z; h_sT[c0 + 3][r] = v.w;
        v = hg[t + 256];
        r = (t + 256) >> 4; c0 = (t & 15) * 4;
        h_sT[c0 + 0][r] = v.x; h_sT[c0 + 1][r] = v.y;
        h_sT[c0 + 2][r] = v.z; h_sT[c0 + 3][r] = v.w;
    }
    __syncthreads();

    const int r0 = (t >> 4) * 2;
    const int o0 = (t & 15) << 2;
    float a0x=0.f,a0y=0.f,a0z=0.f,a0w=0.f;
    float a1x=0.f,a1y=0.f,a1z=0.f,a1w=0.f;
#pragma unroll
    for (int f0 = 0; f0 < 64; f0 += 4) {
        float4 w0 = *(const float4*)&W_s[f0 + 0][o0];
        float4 w1 = *(const float4*)&W_s[f0 + 1][o0];
        float4 w2 = *(const float4*)&W_s[f0 + 2][o0];
        float4 w3 = *(const float4*)&W_s[f0 + 3][o0];
        float2 p0 = *(const float2*)&h_sT[f0 + 0][r0];
        float2 p1 = *(const float2*)&h_sT[f0 + 1][r0];
        float2 p2 = *(const float2*)&h_sT[f0 + 2][r0];
        float2 p3 = *(const float2*)&h_sT[f0 + 3][r0];
        a0x += p0.x*w0.x; a0y += p0.x*w0.y; a0z += p0.x*w0.z; a0w += p0.x*w0.w;
        a1x += p0.y*w0.x; a1y += p0.y*w0.y; a1z += p0.y*w0.z; a1w += p0.y*w0.w;
        a0x += p1.x*w1.x; a0y += p1.x*w1.y; a0z += p1.x*w1.z; a0w += p1.x*w1.w;
        a1x += p1.y*w1.x; a1y += p1.y*w1.y; a1z += p1.y*w1.z; a1w += p1.y*w1.w;
        a0x += p2.x*w2.x; a0y += p2.x*w2.y; a0z += p2.x*w2.z; a0w += p2.x*w2.w;
        a1x += p2.y*w2.x; a1y += p2.y*w2.y; a1z += p2.y*w2.z; a1w += p2.y*w2.w;
        a0x += p3.x*w3.x; a0y += p3.x*w3.y; a0z += p3.x*w3.z; a0w += p3.x*w3.w;
        a1x += p3.y*w3.x; a1y += p3.y*w3.y; a1z += p3.y*w3.z; a1w += p3.y*w3.w;
    }

    // transpose tile (f16)
    tT[o0 + 0][r0] = __float2half_rn(a0x); tT[o0 + 0][r0 + 1] = __float2half_rn(a1x);
    tT[o0 + 1][r0] = __float2half_rn(a0y); tT[o0 + 1][r0 + 1] = __float2half_rn(a1y);
    tT[o0 + 2][r0] = __float2half_rn(a0z); tT[o0 + 2][r0 + 1] = __float2half_rn(a1z);
    tT[o0 + 3][r0] = __float2half_rn(a0w); tT[o0 + 3][r0 + 1] = __float2half_rn(a1w);

    float4 av1 = *(const float4*)&a[o0];
    float4 av2 = *(const float4*)&a[64 + o0];
    red1[r0][t & 15]     = a0x*av1.x + a0y*av1.y + a0z*av1.z + a0w*av1.w;
    red1[r0 + 1][t & 15] = a1x*av1.x + a1y*av1.y + a1z*av1.z + a1w*av1.w;
    red2[r0][t & 15]     = a0x*av2.x + a0y*av2.y + a0z*av2.z + a0w*av2.w;
    red2[r0 + 1][t & 15] = a1x*av2.x + a1y*av2.y + a1z*av2.z + a1w*av2.w;
    __syncthreads();

    if (t < 32) {
        float s1 = 0.f, s2 = 0.f;
#pragma unroll
        for (int k = 0; k < 16; k++) { s1 += red1[t][k]; s2 += red2[t][k]; }
        g_e1pack[row0 + t] = make_float4(s1, __expf(s1), __expf(0.2f * s1), 0.f);
        g_e2pack[row0 + t] = make_float4(s2, __expf(s2), __expf(0.2f * s2), 0.f);
    }

    {
        const int b  = row0 / Nn;
        const int i0 = row0 % Nn;
        const int o  = t >> 2;
        const int rr = (t & 3) * 8;
        *(uint4*)(g_WhT + ((size_t)b * Ff + o) * Nn + i0 + rr) = *(const uint4*)&tT[o][rr];
    }
}

// ---------------------------------------------------------------------------
// Kernel 1b: pack adj>0 into bitmask.
// ---------------------------------------------------------------------------
__global__ __launch_bounds__(256) void bitpack_kernel(const float* __restrict__ adj)
{
    const int lane = threadIdx.x & 31;
    const int row  = (blockIdx.x * 256 + threadIdx.x) >> 5;
    uint32_t* mw = (uint32_t*)g_adjmask;
    const float* arow = adj + (size_t)row * Nn;
#pragma unroll 4
    for (int w = 0; w < 64; w++) {
        float av = __ldg(&arow[w * 32 + lane]);
        uint32_t m = __ballot_sync(0xffffffffu, av > 0.f);
        if (lane == 0) mw[row * 64 + w] = m;
    }
}

// ---------------------------------------------------------------------------
// Kernel 2: fused GAT via HMMA, MTILE=64, 512 thr (16 warps, 16i x 16f tiles).
// Double-buffered cp.async B staging; 1 barrier per step; p-gen one step ahead.
// grid (32, 8) = 256 CTAs -> B L2 traffic 64 MB.
// ---------------------------------------------------------------------------
__global__ __launch_bounds__(512, 1) void gat_hmma(float* __restrict__ out)
{
    __shared__ __align__(128) __half A_s[2][MTILE * 64];   // 2 x 8 KB
    __shared__ __align__(128) __half B_s[2][64 * 64];      // 2 x 8 KB
    __shared__ float e1_s[MTILE], E1p_s[MTILE], E1n_s[MTILE];
    __shared__ float Z_s[MTILE];

    const int t    = threadIdx.x;
    const int lane = t & 31;
    const int wid  = t >> 5;      // 0..15
    const int wm   = wid & 3;     // rows wm*16 .. +15
    const int wn   = wid >> 2;    // cols wn*16 .. +15
    const int i0   = blockIdx.x * MTILE;
    const int b    = blockIdx.y;

    if (t < MTILE) {
        float4 p = g_e1pack[(size_t)b * Nn + i0 + t];
        e1_s[t] = p.x; E1p_s[t] = p.y; E1n_s[t] = p.z;
    }
    __syncthreads();

    const uint32_t Abase = smem_u32(A_s);
    const uint32_t Bbase = smem_u32(B_s);

    const uint32_t xv = (lane & 7) << 4;
    const uint32_t aRowOff = (uint32_t)(wm * 16 + (lane & 7) + ((lane >> 3) & 1) * 8) * 128;
    const uint32_t akbo    = ((lane >> 4) & 1) * 16;
    const uint32_t bRowOff = (uint32_t)(wn * 16 + (lane & 7)) * 128;
    const uint32_t bkbo    = ((lane >> 3) & 1) * 16;

    const __half* whtB = g_WhT + (size_t)b * Ff * Nn;
    const float4* e2p  = g_e2pack + (size_t)b * Nn;
    // cp.async B indexing: thread -> (f = t>>3, chunk c = t&7)
    const int bf_ = t >> 3, bc_ = t & 7;
    const uint32_t bDst = Bbase + swz128((uint32_t)(bf_ * 128 + bc_ * 16));
    const __half* bSrc0 = whtB + (size_t)bf_ * Nn + bc_ * 8;

    float acc[2][4];
#pragma unroll
    for (int nf = 0; nf < 2; nf++)
#pragma unroll
        for (int c = 0; c < 4; c++) acc[nf][c] = 0.f;

    float zpart[4] = {0.f, 0.f, 0.f, 0.f};

    // p-gen lambda-ish macro via explicit code (rows wid*4..+3)
#define PGEN(S, BUF) do {                                                          \
        const int j0_ = (S) * JT;                                                  \
        float4 jp0 = __ldg(&e2p[j0_ + 2 * lane]);                                  \
        float4 jp1 = __ldg(&e2p[j0_ + 2 * lane + 1]);                              \
        _Pragma("unroll")                                                          \
        for (int g = 0; g < 4; g++) {                                              \
            int i = wid * 4 + g;                                                   \
            ull m = __ldg(&g_adjmask[(size_t)(i0 + i) * (Nn / 64) + (S)]);         \
            float e1v = e1_s[i], e1pv = E1p_s[i], e1nv = E1n_s[i];                 \
            float p0 = (e1v + jp0.x > 0.f) ? e1pv * jp0.y : e1nv * jp0.z;          \
            float p1 = (e1v + jp1.x > 0.f) ? e1pv * jp1.y : e1nv * jp1.z;          \
            p0 = ((m >> (2 * lane)) & 1ull)     ? p0 : 0.f;                        \
            p1 = ((m >> (2 * lane + 1)) & 1ull) ? p1 : 0.f;                        \
            __half2 ph = __floats2half2_rn(p0, p1);                                \
            float2 pf = __half22float2(ph);                                        \
            zpart[g] += pf.x + pf.y;                                               \
            *(__half2*)((char*)A_s + (BUF) * 8192 +                                \
                        swz128((uint32_t)(i * 128 + lane * 4))) = ph;              \
        }                                                                          \
    } while (0)

    // prologue: stage B[0], p-gen A[0]
    cp16(bDst, bSrc0);
    CP_COMMIT();
    PGEN(0, 0);

    for (int s = 0; s < NSTEPS; s++) {
        const int cur = s & 1;
        CP_WAIT0();            // B[cur] resident
        __syncthreads();       // A[cur] visible; all warps done with B[cur^1]

        if (s + 1 < NSTEPS) {
            cp16(bDst + (cur ^ 1) * 8192, bSrc0 + (s + 1) * JT);
            CP_COMMIT();
            PGEN(s + 1, cur ^ 1);
        }

        // HMMA on buffers cur
        const uint32_t Ab = Abase + cur * 8192;
        const uint32_t Bbf = cur * 8192;
#pragma unroll
        for (int kf = 0; kf < 4; kf++) {
            const uint32_t kb = kf * 32;
            uint32_t a4[4];
            ldsm_x4(a4[0], a4[1], a4[2], a4[3], Ab + aRowOff + ((kb + akbo) ^ xv));
#pragma unroll
            for (int nf = 0; nf < 2; nf++) {
                uint32_t bfrag[2];
                ldsm_x2(bfrag[0], bfrag[1],
                        Bbase + Bbf + bRowOff + nf * 1024 + ((kb + bkbo) ^ xv));
                mma16816(acc[nf], a4, bfrag);
            }
        }
    }
#undef PGEN

    // reduce Z (warp wid owns rows wid*4..+3)
#pragma unroll
    for (int g = 0; g < 4; g++) {
        float z = zpart[g];
#pragma unroll
        for (int off = 16; off; off >>= 1)
            z += __shfl_xor_sync(0xffffffffu, z, off);
        if (lane == 0) Z_s[wid * 4 + g] = z;
    }
    __syncthreads();

    // epilogue
    {
        const int r_lo = wm * 16 + (lane >> 2);
        const int r_hi = r_lo + 8;
        const float zlo = 1.0f / Z_s[r_lo];
        const float zhi = 1.0f / Z_s[r_hi];
        float* olo = out + ((size_t)b * Nn + i0 + r_lo) * 64;
        float* ohi = out + ((size_t)b * Nn + i0 + r_hi) * 64;
#pragma unroll
        for (int nf = 0; nf < 2; nf++) {
            const int col = wn * 16 + nf * 8 + 2 * (lane & 3);
            float2 v;
            v.x = acc[nf][0] * zlo; v.y = acc[nf][1] * zlo;
            v.x = v.x > 0.f ? v.x : expm1f(v.x);
            v.y = v.y > 0.f ? v.y : expm1f(v.y);
            *(float2*)(olo + col) = v;
            v.x = acc[nf][2] * zhi; v.y = acc[nf][3] * zhi;
            v.x = v.x > 0.f ? v.x : expm1f(v.x);
            v.y = v.y > 0.f ? v.y : expm1f(v.y);
            *(float2*)(ohi + col) = v;
        }
    }
}

// ---------------------------------------------------------------------------
extern "C" void kernel_launch(void* const* d_in, const int* in_sizes, int n_in,
                              void* d_out, int out_size)
{
    const float* h = nullptr; const float* adj = nullptr;
    const float* W = nullptr; const float* a = nullptr;
    for (int i = 0; i < n_in; i++) {
        switch (in_sizes[i]) {
            case Bb * Nn * Ff: h   = (const float*)d_in[i]; break;
            case Nn * Nn:      adj = (const float*)d_in[i]; break;
            case Ff * Ff:      W   = (const float*)d_in[i]; break;
            case 2 * Ff:       a   = (const float*)d_in[i]; break;
            default: break;
        }
    }
    (void)out_size;

    prep_kernel<<<(Bb * Nn) / 32, 256>>>(h, W, a);
    bitpack_kernel<<<Nn / 8, 256>>>(adj);
    gat_hmma<<<dim3(Nn / MTILE, Bb), 512>>>((float*)d_out);
}

// round 12
// speedup vs baseline: 1.2874x; 1.2874x over previous
#include <cuda_runtime.h>
#include <cuda_fp16.h>
#include <math.h>
#include <stdint.h>

#define Bb 8
#define Nn 2048
#define Ff 64
#define MTILE 64
#define JT 64
#define NSTEPS (Nn / JT)        // 32

typedef unsigned long long ull;

// Scratch (device globals)
__device__ __half g_WhT[Bb * Ff * Nn];    // 2 MB f16  [b][f][j]
__device__ float4 g_e1pack[Bb * Nn];      // (e1, exp(e1), exp(0.2 e1), 0)
__device__ float4 g_e2pack[Bb * Nn];      // (e2, exp(e2), exp(0.2 e2), 0)
__device__ ull    g_adjmask[Nn * (Nn / 64)];   // 512 KB bitmask

// ------------------------- helpers ----------------------------
__device__ __forceinline__ uint32_t smem_u32(const void* p) {
    uint32_t a;
    asm("{ .reg .u64 t; cvta.to.shared.u64 t, %1; cvt.u32.u64 %0, t; }" : "=r"(a) : "l"(p));
    return a;
}
__device__ __forceinline__ uint32_t swz128(uint32_t off) {
    return off ^ ((off >> 3) & 0x70);
}
__device__ __forceinline__ void cp16(uint32_t dst, const void* src) {
    asm volatile("cp.async.cg.shared.global [%0], [%1], 16;" :: "r"(dst), "l"(src));
}
#define CP_COMMIT() asm volatile("cp.async.commit_group;" ::: "memory")
#define CP_WAIT0()  asm volatile("cp.async.wait_group 0;" ::: "memory")
__device__ __forceinline__ void ldsm_x4(uint32_t& r0, uint32_t& r1, uint32_t& r2, uint32_t& r3,
                                        uint32_t addr) {
    asm volatile("ldmatrix.sync.aligned.m8n8.x4.shared.b16 {%0,%1,%2,%3}, [%4];"
                 : "=r"(r0), "=r"(r1), "=r"(r2), "=r"(r3) : "r"(addr));
}
__device__ __forceinline__ void ldsm_x2(uint32_t& r0, uint32_t& r1, uint32_t addr) {
    asm volatile("ldmatrix.sync.aligned.m8n8.x2.shared.b16 {%0,%1}, [%2];"
                 : "=r"(r0), "=r"(r1) : "r"(addr));
}
__device__ __forceinline__ void mma16816(float* c, const uint32_t* a, const uint32_t* bf) {
    asm volatile(
        "mma.sync.aligned.m16n8k16.row.col.f32.f16.f16.f32 "
        "{%0,%1,%2,%3}, {%4,%5,%6,%7}, {%8,%9}, {%0,%1,%2,%3};"
        : "+f"(c[0]), "+f"(c[1]), "+f"(c[2]), "+f"(c[3])
        : "r"(a[0]), "r"(a[1]), "r"(a[2]), "r"(a[3]), "r"(bf[0]), "r"(bf[1]));
}

// ---------------------------------------------------------------------------
// Kernel 1: Wh = h @ W^T -> WhT f16 (fused transpose) + e1/e2 exp packs.
// 512 CTAs x 256 thr; 32 rows/CTA; thread = 2 rows x 4 outs.
// Cross-chunk register double-buffer: load chunk k+1, FMA chunk k.
// ---------------------------------------------------------------------------
__global__ __launch_bounds__(256) void prep_kernel(const float* __restrict__ h,
                                                   const float* __restrict__ W,
                                                   const float* __restrict__ a)
{
    __shared__ __align__(16) float W_s[64][64];    // [f][o]
    __shared__ float h_sT[64][34];                 // [f][r]
    __shared__ float red1[32][16];
    __shared__ float red2[32][16];
    __shared__ __align__(16) __half tT[64][40];    // [o][r]

    const int t = threadIdx.x;
    const int row0 = blockIdx.x * 32;

    for (int idx = t; idx < 64 * 64; idx += 256) {
        int o = idx >> 6, f = idx & 63;
        W_s[f][o] = W[idx];                        // W is [o][f]
    }
    {
        const float4* hg = (const float4*)(h + (size_t)row0 * 64);
        float4 v = hg[t];
        int r = t >> 4, c0 = (t & 15) * 4;
        h_sT[c0 + 0][r] = v.x; h_sT[c0 + 1][r] = v.y;
        h_sT[c0 + 2][r] = v.z; h_sT[c0 + 3][r] = v.w;
        v = hg[t + 256];
        r = (t + 256) >> 4; c0 = (t & 15) * 4;
        h_sT[c0 + 0][r] = v.x; h_sT[c0 + 1][r] = v.y;
        h_sT[c0 + 2][r] = v.z; h_sT[c0 + 3][r] = v.w;
    }
    __syncthreads();

    const int r0 = (t >> 4) * 2;
    const int o0 = (t & 15) << 2;
    float a0x=0.f,a0y=0.f,a0z=0.f,a0w=0.f;
    float a1x=0.f,a1y=0.f,a1z=0.f,a1w=0.f;

#define LDC(f0, WW, HH) do {                                   \
        WW[0] = *(const float4*)&W_s[(f0) + 0][o0];            \
        WW[1] = *(const float4*)&W_s[(f0) + 1][o0];            \
        WW[2] = *(const float4*)&W_s[(f0) + 2][o0];            \
        WW[3] = *(const float4*)&W_s[(f0) + 3][o0];            \
        HH[0] = *(const float2*)&h_sT[(f0) + 0][r0];           \
        HH[1] = *(const float2*)&h_sT[(f0) + 1][r0];           \
        HH[2] = *(const float2*)&h_sT[(f0) + 2][r0];           \
        HH[3] = *(const float2*)&h_sT[(f0) + 3][r0];           \
    } while (0)
#define FMAC(WW, HH) do {                                                       \
        _Pragma("unroll")                                                       \
        for (int q = 0; q < 4; q++) {                                           \
            a0x += HH[q].x*WW[q].x; a0y += HH[q].x*WW[q].y;                     \
            a0z += HH[q].x*WW[q].z; a0w += HH[q].x*WW[q].w;                     \
            a1x += HH[q].y*WW[q].x; a1y += HH[q].y*WW[q].y;                     \
            a1z += HH[q].y*WW[q].z; a1w += HH[q].y*WW[q].w;                     \
        }                                                                       \
    } while (0)

    {
        float4 Wa[4], Wb[4];
        float2 Ha[4], Hb[4];
        LDC(0, Wa, Ha);
#pragma unroll
        for (int f0 = 0; f0 < 64; f0 += 8) {
            LDC(f0 + 4, Wb, Hb);
            FMAC(Wa, Ha);
            if (f0 + 8 < 64) LDC(f0 + 8, Wa, Ha);
            FMAC(Wb, Hb);
        }
    }
#undef LDC
#undef FMAC

    tT[o0 + 0][r0] = __float2half_rn(a0x); tT[o0 + 0][r0 + 1] = __float2half_rn(a1x);
    tT[o0 + 1][r0] = __float2half_rn(a0y); tT[o0 + 1][r0 + 1] = __float2half_rn(a1y);
    tT[o0 + 2][r0] = __float2half_rn(a0z); tT[o0 + 2][r0 + 1] = __float2half_rn(a1z);
    tT[o0 + 3][r0] = __float2half_rn(a0w); tT[o0 + 3][r0 + 1] = __float2half_rn(a1w);

    float4 av1 = *(const float4*)&a[o0];
    float4 av2 = *(const float4*)&a[64 + o0];
    red1[r0][t & 15]     = a0x*av1.x + a0y*av1.y + a0z*av1.z + a0w*av1.w;
    red1[r0 + 1][t & 15] = a1x*av1.x + a1y*av1.y + a1z*av1.z + a1w*av1.w;
    red2[r0][t & 15]     = a0x*av2.x + a0y*av2.y + a0z*av2.z + a0w*av2.w;
    red2[r0 + 1][t & 15] = a1x*av2.x + a1y*av2.y + a1z*av2.z + a1w*av2.w;
    __syncthreads();

    if (t < 32) {
        float s1 = 0.f, s2 = 0.f;
#pragma unroll
        for (int k = 0; k < 16; k++) { s1 += red1[t][k]; s2 += red2[t][k]; }
        g_e1pack[row0 + t] = make_float4(s1, __expf(s1), __expf(0.2f * s1), 0.f);
        g_e2pack[row0 + t] = make_float4(s2, __expf(s2), __expf(0.2f * s2), 0.f);
    }

    {
        const int b  = row0 / Nn;
        const int i0 = row0 % Nn;
        const int o  = t >> 2;
        const int rr = (t & 3) * 8;
        *(uint4*)(g_WhT + ((size_t)b * Ff + o) * Nn + i0 + rr) = *(const uint4*)&tT[o][rr];
    }
}

// ---------------------------------------------------------------------------
// Kernel 1b: pack adj>0 into bitmask.
// ---------------------------------------------------------------------------
__global__ __launch_bounds__(256) void bitpack_kernel(const float* __restrict__ adj)
{
    const int lane = threadIdx.x & 31;
    const int row  = (blockIdx.x * 256 + threadIdx.x) >> 5;
    uint32_t* mw = (uint32_t*)g_adjmask;
    const float* arow = adj + (size_t)row * Nn;
#pragma unroll 4
    for (int w = 0; w < 64; w++) {
        float av = __ldg(&arow[w * 32 + lane]);
        uint32_t m = __ballot_sync(0xffffffffu, av > 0.f);
        if (lane == 0) mw[row * 64 + w] = m;
    }
}

// ---------------------------------------------------------------------------
// Kernel 2: fused GAT via HMMA. MTILE=64, 256 thr (8 warps, 16i x 32f tiles),
// 2 CTAs/SM. Double-buffered cp.async B; PGEN inputs register-prefetched one
// full iteration ahead (two alternating sets, loop unrolled x2).
// ---------------------------------------------------------------------------
__global__ __launch_bounds__(256, 2) void gat_hmma(float* __restrict__ out)
{
    __shared__ __align__(128) __half A_s[2][MTILE * 64];   // 2 x 8 KB
    __shared__ __align__(128) __half B_s[2][64 * 64];      // 2 x 8 KB
    __shared__ float e1_s[MTILE], E1p_s[MTILE], E1n_s[MTILE];
    __shared__ float Z_s[MTILE];

    const int t    = threadIdx.x;
    const int lane = t & 31;
    const int wid  = t >> 5;      // 0..7
    const int wm   = wid & 3;     // rows wm*16 .. +15
    const int wn   = wid >> 2;    // cols wn*32 .. +31
    const int i0   = blockIdx.x * MTILE;
    const int b    = blockIdx.y;

    if (t < MTILE) {
        float4 p = g_e1pack[(size_t)b * Nn + i0 + t];
        e1_s[t] = p.x; E1p_s[t] = p.y; E1n_s[t] = p.z;
    }
    __syncthreads();

    const uint32_t Abase = smem_u32(A_s);
    const uint32_t Bbase = smem_u32(B_s);

    const uint32_t xv = (lane & 7) << 4;
    const uint32_t aRowOff = (uint32_t)(wm * 16 + (lane & 7) + ((lane >> 3) & 1) * 8) * 128;
    const uint32_t akbo    = ((lane >> 4) & 1) * 16;
    const uint32_t bRowOff = (uint32_t)(wn * 32 + (lane & 7)) * 128;
    const uint32_t bkbo    = ((lane >> 3) & 1) * 16;

    const __half* whtB = g_WhT + (size_t)b * Ff * Nn;
    const float4* e2p  = g_e2pack + (size_t)b * Nn;

    // cp.async B: 512 chunks / 256 thr -> 2 per thread
    const int bf1 = t >> 3, bc1 = t & 7;
    const int bf2 = (t + 256) >> 3;
    const uint32_t bDst1 = Bbase + swz128((uint32_t)(bf1 * 128 + bc1 * 16));
    const uint32_t bDst2 = Bbase + swz128((uint32_t)(bf2 * 128 + bc1 * 16));
    const __half* bSrc1 = whtB + (size_t)bf1 * Nn + bc1 * 8;
    const __half* bSrc2 = whtB + (size_t)bf2 * Nn + bc1 * 8;

#define CPB(S, BUF) do {                                  \
        cp16(bDst1 + (BUF) * 8192, bSrc1 + (S) * JT);     \
        cp16(bDst2 + (BUF) * 8192, bSrc2 + (S) * JT);     \
        CP_COMMIT();                                      \
    } while (0)

    float acc[4][4];
#pragma unroll
    for (int nf = 0; nf < 4; nf++)
#pragma unroll
        for (int c = 0; c < 4; c++) acc[nf][c] = 0.f;

    float zpart[8];
#pragma unroll
    for (int g = 0; g < 8; g++) zpart[g] = 0.f;

#define LOAD_SET(S, JP0, JP1, MM) do {                                           \
        JP0 = __ldg(&e2p[(S) * JT + 2 * lane]);                                  \
        JP1 = __ldg(&e2p[(S) * JT + 2 * lane + 1]);                              \
        _Pragma("unroll")                                                        \
        for (int g = 0; g < 8; g++)                                              \
            MM[g] = __ldg(&g_adjmask[(size_t)(i0 + wid * 8 + g) * (Nn / 64) + (S)]); \
    } while (0)

#define PGEN_C(JP0, JP1, MM, BUF) do {                                           \
        _Pragma("unroll")                                                        \
        for (int g = 0; g < 8; g++) {                                            \
            int i = wid * 8 + g;                                                 \
            float e1v = e1_s[i], e1pv = E1p_s[i], e1nv = E1n_s[i];               \
            float p0 = (e1v + JP0.x > 0.f) ? e1pv * JP0.y : e1nv * JP0.z;        \
            float p1 = (e1v + JP1.x > 0.f) ? e1pv * JP1.y : e1nv * JP1.z;        \
            p0 = ((MM[g] >> (2 * lane)) & 1ull)     ? p0 : 0.f;                  \
            p1 = ((MM[g] >> (2 * lane + 1)) & 1ull) ? p1 : 0.f;                  \
            __half2 ph = __floats2half2_rn(p0, p1);                              \
            float2 pf = __half22float2(ph);                                      \
            zpart[g] += pf.x + pf.y;                                             \
            *(__half2*)((char*)A_s + (BUF) * 8192 +                              \
                        swz128((uint32_t)(i * 128 + lane * 4))) = ph;            \
        }                                                                        \
    } while (0)

#define HMMA(BUF) do {                                                           \
        const uint32_t Ab_ = Abase + (BUF) * 8192;                               \
        const uint32_t Bb_ = Bbase + (BUF) * 8192;                               \
        _Pragma("unroll")                                                        \
        for (int kf = 0; kf < 4; kf++) {                                         \
            const uint32_t kb = kf * 32;                                         \
            uint32_t a4[4];                                                      \
            ldsm_x4(a4[0], a4[1], a4[2], a4[3], Ab_ + aRowOff + ((kb + akbo) ^ xv)); \
            _Pragma("unroll")                                                    \
            for (int nf = 0; nf < 4; nf++) {                                     \
                uint32_t bfrag[2];                                               \
                ldsm_x2(bfrag[0], bfrag[1],                                      \
                        Bb_ + bRowOff + nf * 1024 + ((kb + bkbo) ^ xv));         \
                mma16816(acc[nf], a4, bfrag);                                    \
            }                                                                    \
        }                                                                        \
    } while (0)

    float4 jpA0, jpA1, jpB0, jpB1;
    ull mA[8], mB[8];

    // prologue: B[0] in flight, PGEN step0 -> buf0, prefetch set for step1
    CPB(0, 0);
    LOAD_SET(0, jpA0, jpA1, mA);
    PGEN_C(jpA0, jpA1, mA, 0);
    LOAD_SET(1, jpB0, jpB1, mB);

#pragma unroll 1
    for (int s = 0; s < NSTEPS; s += 2) {
        // even sub-iter: consume setB (step s+1), buffers: cur=0
        CP_WAIT0();
        __syncthreads();
        CPB(s + 1, 1);
        PGEN_C(jpB0, jpB1, mB, 1);
        if (s + 2 < NSTEPS) LOAD_SET(s + 2, jpA0, jpA1, mA);
        HMMA(0);

        // odd sub-iter: consume setA (step s+2), cur=1
        CP_WAIT0();
        __syncthreads();
        if (s + 2 < NSTEPS) {
            CPB(s + 2, 0);
            PGEN_C(jpA0, jpA1, mA, 0);
            if (s + 3 < NSTEPS) LOAD_SET(s + 3, jpB0, jpB1, mB);
        }
        HMMA(1);
    }
#undef CPB
#undef LOAD_SET
#undef PGEN_C
#undef HMMA

    // reduce Z (warp wid owns rows wid*8..+7)
#pragma unroll
    for (int g = 0; g < 8; g++) {
        float z = zpart[g];
#pragma unroll
        for (int off = 16; off; off >>= 1)
            z += __shfl_xor_sync(0xffffffffu, z, off);
        if (lane == 0) Z_s[wid * 8 + g] = z;
    }
    __syncthreads();

    // epilogue
    {
        const int r_lo = wm * 16 + (lane >> 2);
        const int r_hi = r_lo + 8;
        const float zlo = 1.0f / Z_s[r_lo];
        const float zhi = 1.0f / Z_s[r_hi];
        float* olo = out + ((size_t)b * Nn + i0 + r_lo) * 64;
        float* ohi = out + ((size_t)b * Nn + i0 + r_hi) * 64;
#pragma unroll
        for (int nf = 0; nf < 4; nf++) {
            const int col = wn * 32 + nf * 8 + 2 * (lane & 3);
            float2 v;
            v.x = acc[nf][0] * zlo; v.y = acc[nf][1] * zlo;
            v.x = v.x > 0.f ? v.x : expm1f(v.x);
            v.y = v.y > 0.f ? v.y : expm1f(v.y);
            *(float2*)(olo + col) = v;
            v.x = acc[nf][2] * zhi; v.y = acc[nf][3] * zhi;
            v.x = v.x > 0.f ? v.x : expm1f(v.x);
            v.y = v.y > 0.f ? v.y : expm1f(v.y);
            *(float2*)(ohi + col) = v;
        }
    }
}

// ---------------------------------------------------------------------------
extern "C" void kernel_launch(void* const* d_in, const int* in_sizes, int n_in,
                              void* d_out, int out_size)
{
    const float* h = nullptr; const float* adj = nullptr;
    const float* W = nullptr; const float* a = nullptr;
    for (int i = 0; i < n_in; i++) {
        switch (in_sizes[i]) {
            case Bb * Nn * Ff: h   = (const float*)d_in[i]; break;
            case Nn * Nn:      adj = (const float*)d_in[i]; break;
            case Ff * Ff:      W   = (const float*)d_in[i]; break;
            case 2 * Ff:       a   = (const float*)d_in[i]; break;
            default: break;
        }
    }
    (void)out_size;

    prep_kernel<<<(Bb * Nn) / 32, 256>>>(h, W, a);
    bitpack_kernel<<<Nn / 8, 256>>>(adj);
    gat_hmma<<<dim3(Nn / MTILE, Bb), 256>>>((float*)d_out);
}

// round 13
// speedup vs baseline: 1.4805x; 1.1501x over previous
#include <cuda_runtime.h>
#include <cuda_fp16.h>
#include <math.h>
#include <stdint.h>

#define Bb 8
#define Nn 2048
#define Ff 64
#define MTILE 64
#define JT 64
#define NSTEPS (Nn / JT)        // 32

typedef unsigned long long ull;

// Scratch (device globals)
__device__ __half g_WhT[Bb * Ff * Nn];    // 2 MB f16  [b][f][j]
__device__ float4 g_e1pack[Bb * Nn];      // (e1, exp(e1), exp(0.2 e1), 0)
__device__ float4 g_e2pack[Bb * Nn];      // (e2, exp(e2), exp(0.2 e2), 0)
__device__ ull    g_adjmask[Nn * (Nn / 64)];   // 512 KB bitmask

// ------------------------- helpers ----------------------------
__device__ __forceinline__ uint32_t smem_u32(const void* p) {
    uint32_t a;
    asm("{ .reg .u64 t; cvta.to.shared.u64 t, %1; cvt.u32.u64 %0, t; }" : "=r"(a) : "l"(p));
    return a;
}
__device__ __forceinline__ uint32_t swz128(uint32_t off) {
    return off ^ ((off >> 3) & 0x70);
}
__device__ __forceinline__ void cp16(uint32_t dst, const void* src) {
    asm volatile("cp.async.cg.shared.global [%0], [%1], 16;" :: "r"(dst), "l"(src));
}
#define CP_COMMIT() asm volatile("cp.async.commit_group;" ::: "memory")
#define CP_WAIT0()  asm volatile("cp.async.wait_group 0;" ::: "memory")
__device__ __forceinline__ void ldsm_x4(uint32_t& r0, uint32_t& r1, uint32_t& r2, uint32_t& r3,
                                        uint32_t addr) {
    asm volatile("ldmatrix.sync.aligned.m8n8.x4.shared.b16 {%0,%1,%2,%3}, [%4];"
                 : "=r"(r0), "=r"(r1), "=r"(r2), "=r"(r3) : "r"(addr));
}
__device__ __forceinline__ void ldsm_x2(uint32_t& r0, uint32_t& r1, uint32_t addr) {
    asm volatile("ldmatrix.sync.aligned.m8n8.x2.shared.b16 {%0,%1}, [%2];"
                 : "=r"(r0), "=r"(r1) : "r"(addr));
}
__device__ __forceinline__ void mma16816(float* c, const uint32_t* a, const uint32_t* bf) {
    asm volatile(
        "mma.sync.aligned.m16n8k16.row.col.f32.f16.f16.f32 "
        "{%0,%1,%2,%3}, {%4,%5,%6,%7}, {%8,%9}, {%0,%1,%2,%3};"
        : "+f"(c[0]), "+f"(c[1]), "+f"(c[2]), "+f"(c[3])
        : "r"(a[0]), "r"(a[1]), "r"(a[2]), "r"(a[3]), "r"(bf[0]), "r"(bf[1]));
}

// ---------------------------------------------------------------------------
// Kernel 1 (rewritten): Wh via HMMA.
// CTA = 128 thr (4 warps), 64 rows. grid = 256 CTAs.
// cp.async stages h (fp32) + W (fp32); B = f16(W) [o][f] swizzled;
// A = f16(h) [r][f] swizzled; e1/e2 computed fp32 via u = W^T a during the
// h conversion pass. HMMA 16 rows/warp x 64 cols. C -> f16 transpose tile
// (aliased over dead h32) -> g_WhT.
// ---------------------------------------------------------------------------
__global__ __launch_bounds__(128) void prep_kernel(const float* __restrict__ h,
                                                   const float* __restrict__ W,
                                                   const float* __restrict__ a)
{
    __shared__ __align__(128) char reg1[16384];    // W32 (fp32) -> A_s (f16 swz)
    __shared__ __align__(128) char reg2[16384];    // h32 (fp32) -> tT (f16 [o][72])
    __shared__ __align__(128) __half B_s[64 * 64]; // 8 KB swz
    __shared__ float u1_s[64], u2_s[64];

    float* W32 = (float*)reg1;
    float* h32 = (float*)reg2;
    __half* A_s = (__half*)reg1;
    __half* tT  = (__half*)reg2;                   // stride 72 halfs (144 B rows)

    const int t    = threadIdx.x;
    const int lane = t & 31;
    const int w    = t >> 5;          // warp 0..3
    const int row0 = blockIdx.x * 64; // global row in [0, 16384)

    const uint32_t r1b = smem_u32(reg1);
    const uint32_t r2b = smem_u32(reg2);
    const uint32_t Bb_ = smem_u32(B_s);

    // ---- stage W (16 KB) + h (16 KB) via cp.async, flat ----
    {
        const char* Wsrc = (const char*)W;
        const char* hsrc = (const char*)(h + (size_t)row0 * 64);
#pragma unroll
        for (int q = 0; q < 8; q++) {
            cp16(r1b + (t + q * 128) * 16, Wsrc + (t + q * 128) * 16);
            cp16(r2b + (t + q * 128) * 16, hsrc + (t + q * 128) * 16);
        }
        CP_COMMIT();
        CP_WAIT0();
    }
    __syncthreads();

    // ---- phase 1: B = f16(W32) swizzled; u1/u2 = W^T a (fp32) ----
    {
        // B convert: thread -> o = t>>1, f half = (t&1)*32
        const int o = t >> 1, fh = (t & 1) * 32;
        const float* src = W32 + o * 64 + fh;
#pragma unroll
        for (int fo = 0; fo < 16; fo++) {
            float2 v = *(const float2*)(src + 2 * fo);
            *(__half2*)((char*)B_s + swz128((uint32_t)(o * 128 + fh * 2 + fo * 4))) =
                __floats2half2_rn(v.x, v.y);
        }
        // u: warps 0-1 -> u1 (f = t), warps 2-3 -> u2 (f = t-64)
        const int half = t >> 6, f = t & 63;
        const float* ap = a + half * 64;
        float acc = 0.f;
#pragma unroll 8
        for (int o2 = 0; o2 < 64; o2++)
            acc += W32[o2 * 64 + f] * __ldg(&ap[o2]);
        if (half == 0) u1_s[f] = acc; else u2_s[f] = acc;
    }
    __syncthreads();

    // ---- phase 2: A = f16(h32) swizzled (destroys W32); e partials ----
    {
        const int r = t >> 1, fh = (t & 1) * 32;
        const float* src = h32 + r * 64 + fh;
        float acc1 = 0.f, acc2 = 0.f;
#pragma unroll
        for (int fo = 0; fo < 16; fo++) {
            float2 v = *(const float2*)(src + 2 * fo);
            int f = fh + 2 * fo;
            acc1 += v.x * u1_s[f] + v.y * u1_s[f + 1];
            acc2 += v.x * u2_s[f] + v.y * u2_s[f + 1];
            *(__half2*)((char*)A_s + swz128((uint32_t)(r * 128 + fh * 2 + fo * 4))) =
                __floats2half2_rn(v.x, v.y);
        }
        acc1 += __shfl_xor_sync(0xffffffffu, acc1, 1);
        acc2 += __shfl_xor_sync(0xffffffffu, acc2, 1);
        if ((t & 1) == 0) {
            g_e1pack[row0 + r] = make_float4(acc1, __expf(acc1), __expf(0.2f * acc1), 0.f);
            g_e2pack[row0 + r] = make_float4(acc2, __expf(acc2), __expf(0.2f * acc2), 0.f);
        }
    }
    __syncthreads();

    // ---- HMMA: warp w -> rows w*16..+15, all 64 cols (8 n-frags) ----
    float acc[8][4];
#pragma unroll
    for (int nf = 0; nf < 8; nf++)
#pragma unroll
        for (int c = 0; c < 4; c++) acc[nf][c] = 0.f;

    {
        const uint32_t xv = (lane & 7) << 4;
        const uint32_t aRowOff = (uint32_t)(w * 16 + (lane & 7) + ((lane >> 3) & 1) * 8) * 128;
        const uint32_t akbo    = ((lane >> 4) & 1) * 16;
        const uint32_t bRow    = (uint32_t)(lane & 7) * 128;
        const uint32_t bkbo    = ((lane >> 3) & 1) * 16;
#pragma unroll
        for (int kf = 0; kf < 4; kf++) {
            const uint32_t kb = kf * 32;
            uint32_t a4[4];
            ldsm_x4(a4[0], a4[1], a4[2], a4[3], r1b + aRowOff + ((kb + akbo) ^ xv));
#pragma unroll
            for (int nf = 0; nf < 8; nf++) {
                uint32_t bfrag[2];
                ldsm_x2(bfrag[0], bfrag[1], Bb_ + bRow + nf * 1024 + ((kb + bkbo) ^ xv));
                mma16816(acc[nf], a4, bfrag);
            }
        }
    }
    __syncthreads();       // h32 reads done everywhere; safe to write tT

    // ---- C frags -> f16 transpose tile tT[o][r] ----
    {
        const int r_lo = w * 16 + (lane >> 2);
        const int r_hi = r_lo + 8;
#pragma unroll
        for (int nf = 0; nf < 8; nf++) {
            const int c0 = nf * 8 + 2 * (lane & 3);
            tT[(c0 + 0) * 72 + r_lo] = __float2half_rn(acc[nf][0]);
            tT[(c0 + 1) * 72 + r_lo] = __float2half_rn(acc[nf][1]);
            tT[(c0 + 0) * 72 + r_hi] = __float2half_rn(acc[nf][2]);
            tT[(c0 + 1) * 72 + r_hi] = __float2half_rn(acc[nf][3]);
        }
    }
    __syncthreads();

    // ---- write WhT: thread -> o = t>>1, r half = (t&1)*32, 4 x uint4 ----
    {
        const int b  = row0 / Nn;
        const int i0 = row0 % Nn;
        const int o  = t >> 1;
        const int rp = (t & 1) * 32;
        __half* dst = g_WhT + ((size_t)b * Ff + o) * Nn + i0 + rp;
#pragma unroll
        for (int q = 0; q < 4; q++)
            *(uint4*)(dst + q * 8) = *(const uint4*)&tT[o * 72 + rp + q * 8];
    }
}

// ---------------------------------------------------------------------------
// Kernel 1b: pack adj>0 into bitmask.
// ---------------------------------------------------------------------------
__global__ __launch_bounds__(256) void bitpack_kernel(const float* __restrict__ adj)
{
    const int lane = threadIdx.x & 31;
    const int row  = (blockIdx.x * 256 + threadIdx.x) >> 5;
    uint32_t* mw = (uint32_t*)g_adjmask;
    const float* arow = adj + (size_t)row * Nn;
#pragma unroll 4
    for (int w = 0; w < 64; w++) {
        float av = __ldg(&arow[w * 32 + lane]);
        uint32_t m = __ballot_sync(0xffffffffu, av > 0.f);
        if (lane == 0) mw[row * 64 + w] = m;
    }
}

// ---------------------------------------------------------------------------
// Kernel 2: fused GAT via HMMA (unchanged from R12).
// ---------------------------------------------------------------------------
__global__ __launch_bounds__(256, 2) void gat_hmma(float* __restrict__ out)
{
    __shared__ __align__(128) __half A_s[2][MTILE * 64];   // 2 x 8 KB
    __shared__ __align__(128) __half B_s[2][64 * 64];      // 2 x 8 KB
    __shared__ float e1_s[MTILE], E1p_s[MTILE], E1n_s[MTILE];
    __shared__ float Z_s[MTILE];

    const int t    = threadIdx.x;
    const int lane = t & 31;
    const int wid  = t >> 5;      // 0..7
    const int wm   = wid & 3;     // rows wm*16 .. +15
    const int wn   = wid >> 2;    // cols wn*32 .. +31
    const int i0   = blockIdx.x * MTILE;
    const int b    = blockIdx.y;

    if (t < MTILE) {
        float4 p = g_e1pack[(size_t)b * Nn + i0 + t];
        e1_s[t] = p.x; E1p_s[t] = p.y; E1n_s[t] = p.z;
    }
    __syncthreads();

    const uint32_t Abase = smem_u32(A_s);
    const uint32_t Bbase = smem_u32(B_s);

    const uint32_t xv = (lane & 7) << 4;
    const uint32_t aRowOff = (uint32_t)(wm * 16 + (lane & 7) + ((lane >> 3) & 1) * 8) * 128;
    const uint32_t akbo    = ((lane >> 4) & 1) * 16;
    const uint32_t bRowOff = (uint32_t)(wn * 32 + (lane & 7)) * 128;
    const uint32_t bkbo    = ((lane >> 3) & 1) * 16;

    const __half* whtB = g_WhT + (size_t)b * Ff * Nn;
    const float4* e2p  = g_e2pack + (size_t)b * Nn;

    const int bf1 = t >> 3, bc1 = t & 7;
    const int bf2 = (t + 256) >> 3;
    const uint32_t bDst1 = Bbase + swz128((uint32_t)(bf1 * 128 + bc1 * 16));
    const uint32_t bDst2 = Bbase + swz128((uint32_t)(bf2 * 128 + bc1 * 16));
    const __half* bSrc1 = whtB + (size_t)bf1 * Nn + bc1 * 8;
    const __half* bSrc2 = whtB + (size_t)bf2 * Nn + bc1 * 8;

#define CPB(S, BUF) do {                                  \
        cp16(bDst1 + (BUF) * 8192, bSrc1 + (S) * JT);     \
        cp16(bDst2 + (BUF) * 8192, bSrc2 + (S) * JT);     \
        CP_COMMIT();                                      \
    } while (0)

    float acc[4][4];
#pragma unroll
    for (int nf = 0; nf < 4; nf++)
#pragma unroll
        for (int c = 0; c < 4; c++) acc[nf][c] = 0.f;

    float zpart[8];
#pragma unroll
    for (int g = 0; g < 8; g++) zpart[g] = 0.f;

#define LOAD_SET(S, JP0, JP1, MM) do {                                           \
        JP0 = __ldg(&e2p[(S) * JT + 2 * lane]);                                  \
        JP1 = __ldg(&e2p[(S) * JT + 2 * lane + 1]);                              \
        _Pragma("unroll")                                                        \
        for (int g = 0; g < 8; g++)                                              \
            MM[g] = __ldg(&g_adjmask[(size_t)(i0 + wid * 8 + g) * (Nn / 64) + (S)]); \
    } while (0)

#define PGEN_C(JP0, JP1, MM, BUF) do {                                           \
        _Pragma("unroll")                                                        \
        for (int g = 0; g < 8; g++) {                                            \
            int i = wid * 8 + g;                                                 \
            float e1v = e1_s[i], e1pv = E1p_s[i], e1nv = E1n_s[i];               \
            float p0 = (e1v + JP0.x > 0.f) ? e1pv * JP0.y : e1nv * JP0.z;        \
            float p1 = (e1v + JP1.x > 0.f) ? e1pv * JP1.y : e1nv * JP1.z;        \
            p0 = ((MM[g] >> (2 * lane)) & 1ull)     ? p0 : 0.f;                  \
            p1 = ((MM[g] >> (2 * lane + 1)) & 1ull) ? p1 : 0.f;                  \
            __half2 ph = __floats2half2_rn(p0, p1);                              \
            float2 pf = __half22float2(ph);                                      \
            zpart[g] += pf.x + pf.y;                                             \
            *(__half2*)((char*)A_s + (BUF) * 8192 +                              \
                        swz128((uint32_t)(i * 128 + lane * 4))) = ph;            \
        }                                                                        \
    } while (0)

#define HMMA(BUF) do {                                                           \
        const uint32_t Ab_ = Abase + (BUF) * 8192;                               \
        const uint32_t Bb_ = Bbase + (BUF) * 8192;                               \
        _Pragma("unroll")                                                        \
        for (int kf = 0; kf < 4; kf++) {                                         \
            const uint32_t kb = kf * 32;                                         \
            uint32_t a4[4];                                                      \
            ldsm_x4(a4[0], a4[1], a4[2], a4[3], Ab_ + aRowOff + ((kb + akbo) ^ xv)); \
            _Pragma("unroll")                                                    \
            for (int nf = 0; nf < 4; nf++) {                                     \
                uint32_t bfrag[2];                                               \
                ldsm_x2(bfrag[0], bfrag[1],                                      \
                        Bb_ + bRowOff + nf * 1024 + ((kb + bkbo) ^ xv));         \
                mma16816(acc[nf], a4, bfrag);                                    \
            }                                                                    \
        }                                                                        \
    } while (0)

    float4 jpA0, jpA1, jpB0, jpB1;
    ull mA[8], mB[8];

    CPB(0, 0);
    LOAD_SET(0, jpA0, jpA1, mA);
    PGEN_C(jpA0, jpA1, mA, 0);
    LOAD_SET(1, jpB0, jpB1, mB);

#pragma unroll 1
    for (int s = 0; s < NSTEPS; s += 2) {
        CP_WAIT0();
        __syncthreads();
        CPB(s + 1, 1);
        PGEN_C(jpB0, jpB1, mB, 1);
        if (s + 2 < NSTEPS) LOAD_SET(s + 2, jpA0, jpA1, mA);
        HMMA(0);

        CP_WAIT0();
        __syncthreads();
        if (s + 2 < NSTEPS) {
            CPB(s + 2, 0);
            PGEN_C(jpA0, jpA1, mA, 0);
            if (s + 3 < NSTEPS) LOAD_SET(s + 3, jpB0, jpB1, mB);
        }
        HMMA(1);
    }
#undef CPB
#undef LOAD_SET
#undef PGEN_C
#undef HMMA

#pragma unroll
    for (int g = 0; g < 8; g++) {
        float z = zpart[g];
#pragma unroll
        for (int off = 16; off; off >>= 1)
            z += __shfl_xor_sync(0xffffffffu, z, off);
        if (lane == 0) Z_s[wid * 8 + g] = z;
    }
    __syncthreads();

    {
        const int r_lo = wm * 16 + (lane >> 2);
        const int r_hi = r_lo + 8;
        const float zlo = 1.0f / Z_s[r_lo];
        const float zhi = 1.0f / Z_s[r_hi];
        float* olo = out + ((size_t)b * Nn + i0 + r_lo) * 64;
        float* ohi = out + ((size_t)b * Nn + i0 + r_hi) * 64;
#pragma unroll
        for (int nf = 0; nf < 4; nf++) {
            const int col = wn * 32 + nf * 8 + 2 * (lane & 3);
            float2 v;
            v.x = acc[nf][0] * zlo; v.y = acc[nf][1] * zlo;
            v.x = v.x > 0.f ? v.x : expm1f(v.x);
            v.y = v.y > 0.f ? v.y : expm1f(v.y);
            *(float2*)(olo + col) = v;
            v.x = acc[nf][2] * zhi; v.y = acc[nf][3] * zhi;
            v.x = v.x > 0.f ? v.x : expm1f(v.x);
            v.y = v.y > 0.f ? v.y : expm1f(v.y);
            *(float2*)(ohi + col) = v;
        }
    }
}

// ---------------------------------------------------------------------------
extern "C" void kernel_launch(void* const* d_in, const int* in_sizes, int n_in,
                              void* d_out, int out_size)
{
    const float* h = nullptr; const float* adj = nullptr;
    const float* W = nullptr; const float* a = nullptr;
    for (int i = 0; i < n_in; i++) {
        switch (in_sizes[i]) {
            case Bb * Nn * Ff: h   = (const float*)d_in[i]; break;
            case Nn * Nn:      adj = (const float*)d_in[i]; break;
            case Ff * Ff:      W   = (const float*)d_in[i]; break;
            case 2 * Ff:       a   = (const float*)d_in[i]; break;
            default: break;
        }
    }
    (void)out_size;

    prep_kernel<<<(Bb * Nn) / 64, 128>>>(h, W, a);
    bitpack_kernel<<<Nn / 8, 256>>>(adj);
    gat_hmma<<<dim3(Nn / MTILE, Bb), 256>>>((float*)d_out);
}

// round 14
// speedup vs baseline: 1.4882x; 1.0052x over previous
#include <cuda_runtime.h>
#include <cuda_fp16.h>
#include <math.h>
#include <stdint.h>

#define Bb 8
#define Nn 2048
#define Ff 64
#define MTILE 64
#define JT 64
#define NSTEPS (Nn / JT)        // 32

#define PREP_CTAS 512           // 32 rows each
#define PACK_CTAS 512           // 4 adj rows each

typedef unsigned long long ull;

// Scratch (device globals)
__device__ __half g_WhT[Bb * Ff * Nn];    // 2 MB f16  [b][f][j]
__device__ float4 g_e1pack[Bb * Nn];      // (e1, exp(e1), exp(0.2 e1), 0)
__device__ float4 g_e2pack[Bb * Nn];      // (e2, exp(e2), exp(0.2 e2), 0)
__device__ ull    g_adjmask[Nn * (Nn / 64)];   // 512 KB bitmask

// ------------------------- helpers ----------------------------
__device__ __forceinline__ uint32_t smem_u32(const void* p) {
    uint32_t a;
    asm("{ .reg .u64 t; cvta.to.shared.u64 t, %1; cvt.u32.u64 %0, t; }" : "=r"(a) : "l"(p));
    return a;
}
__device__ __forceinline__ uint32_t swz128(uint32_t off) {
    return off ^ ((off >> 3) & 0x70);
}
__device__ __forceinline__ void cp16(uint32_t dst, const void* src) {
    asm volatile("cp.async.cg.shared.global [%0], [%1], 16;" :: "r"(dst), "l"(src));
}
#define CP_COMMIT() asm volatile("cp.async.commit_group;" ::: "memory")
#define CP_WAIT0()  asm volatile("cp.async.wait_group 0;" ::: "memory")
__device__ __forceinline__ void ldsm_x4(uint32_t& r0, uint32_t& r1, uint32_t& r2, uint32_t& r3,
                                        uint32_t addr) {
    asm volatile("ldmatrix.sync.aligned.m8n8.x4.shared.b16 {%0,%1,%2,%3}, [%4];"
                 : "=r"(r0), "=r"(r1), "=r"(r2), "=r"(r3) : "r"(addr));
}
__device__ __forceinline__ void mma16816(float* c, const uint32_t* a, const uint32_t* bf) {
    asm volatile(
        "mma.sync.aligned.m16n8k16.row.col.f32.f16.f16.f32 "
        "{%0,%1,%2,%3}, {%4,%5,%6,%7}, {%8,%9}, {%0,%1,%2,%3};"
        : "+f"(c[0]), "+f"(c[1]), "+f"(c[2]), "+f"(c[3])
        : "r"(a[0]), "r"(a[1]), "r"(a[2]), "r"(a[3]), "r"(bf[0]), "r"(bf[1]));
}

// ---------------------------------------------------------------------------
// Kernel 1 (merged): CTAs [0, PREP_CTAS): Wh/e-pack prep (32 rows each).
//                    CTAs [PREP_CTAS, +PACK_CTAS): adj bitmask (4 rows each).
// 128 threads. Both halves run concurrently in one launch.
// ---------------------------------------------------------------------------
__global__ __launch_bounds__(128) void prep_pack_kernel(const float* __restrict__ h,
                                                        const float* __restrict__ W,
                                                        const float* __restrict__ a,
                                                        const float* __restrict__ adj)
{
    const int t    = threadIdx.x;
    const int lane = t & 31;
    const int w    = t >> 5;

    if (blockIdx.x >= PREP_CTAS) {
        // ---------------- bitpack part: 4 rows per CTA ----------------
        const int row = (blockIdx.x - PREP_CTAS) * 4 + w;
        uint32_t* mw = (uint32_t*)g_adjmask;
        const float* arow = adj + (size_t)row * Nn;
#pragma unroll 4
        for (int c = 0; c < 64; c++) {
            float av = __ldg(&arow[c * 32 + lane]);
            uint32_t m = __ballot_sync(0xffffffffu, av > 0.f);
            if (lane == 0) mw[row * 64 + c] = m;
        }
        return;
    }

    // ---------------- prep part: 32 rows per CTA ----------------
    __shared__ __align__(128) char reg1[16384];    // W32 (fp32) -> A_s (f16 swz, 4 KB)
    __shared__ __align__(128) char reg2[8192];     // h32 (fp32) -> tT (f16 [o][40])
    __shared__ __align__(128) __half B_s[64 * 64]; // 8 KB swz
    __shared__ float u1_s[64], u2_s[64];

    float* W32 = (float*)reg1;
    float* h32 = (float*)reg2;
    __half* tT = (__half*)reg2;                    // stride 40 halfs (80 B)

    const int row0 = blockIdx.x * 32;              // global row in [0, 16384)

    const uint32_t r1b = smem_u32(reg1);
    const uint32_t r2b = smem_u32(reg2);
    const uint32_t Bsb = smem_u32(B_s);

    // stage W (16 KB) + h (8 KB)
    {
        const char* Wsrc = (const char*)W;
        const char* hsrc = (const char*)(h + (size_t)row0 * 64);
#pragma unroll
        for (int q = 0; q < 8; q++)
            cp16(r1b + (t + q * 128) * 16, Wsrc + (t + q * 128) * 16);
#pragma unroll
        for (int q = 0; q < 4; q++)
            cp16(r2b + (t + q * 128) * 16, hsrc + (t + q * 128) * 16);
        CP_COMMIT();
        CP_WAIT0();
    }
    __syncthreads();

    // phase 1: B = f16(W32) swizzled; u1/u2 = W^T a (fp32)
    {
        const int o = t >> 1, fh = (t & 1) * 32;
        const float* src = W32 + o * 64 + fh;
#pragma unroll
        for (int fo = 0; fo < 16; fo++) {
            float2 v = *(const float2*)(src + 2 * fo);
            *(__half2*)((char*)B_s + swz128((uint32_t)(o * 128 + fh * 2 + fo * 4))) =
                __floats2half2_rn(v.x, v.y);
        }
        const int half = t >> 6, f = t & 63;
        const float* ap = a + half * 64;
        float acc = 0.f;
#pragma unroll 8
        for (int o2 = 0; o2 < 64; o2++)
            acc += W32[o2 * 64 + f] * __ldg(&ap[o2]);
        if (half == 0) u1_s[f] = acc; else u2_s[f] = acc;
    }
    __syncthreads();

    // phase 2: A = f16(h32) swizzled (overwrites W32); e partials over 16 f's
    {
        const int r = t >> 2, fh = (t & 3) * 16;
        const float* src = h32 + r * 64 + fh;
        float acc1 = 0.f, acc2 = 0.f;
#pragma unroll
        for (int fo = 0; fo < 8; fo++) {
            float2 v = *(const float2*)(src + 2 * fo);
            int f = fh + 2 * fo;
            acc1 += v.x * u1_s[f] + v.y * u1_s[f + 1];
            acc2 += v.x * u2_s[f] + v.y * u2_s[f + 1];
            *(__half2*)((char*)reg1 + swz128((uint32_t)(r * 128 + fh * 2 + fo * 4))) =
                __floats2half2_rn(v.x, v.y);
        }
        acc1 += __shfl_xor_sync(0xffffffffu, acc1, 1);
        acc1 += __shfl_xor_sync(0xffffffffu, acc1, 2);
        acc2 += __shfl_xor_sync(0xffffffffu, acc2, 1);
        acc2 += __shfl_xor_sync(0xffffffffu, acc2, 2);
        if ((t & 3) == 0) {
            g_e1pack[row0 + r] = make_float4(acc1, __expf(acc1), __expf(0.2f * acc1), 0.f);
            g_e2pack[row0 + r] = make_float4(acc2, __expf(acc2), __expf(0.2f * acc2), 0.f);
        }
    }
    __syncthreads();

    // HMMA: warp w: wm = w&1 -> rows wm*16..+15; wn = w>>1 -> cols wn*32..+31
    float acc[4][4];
#pragma unroll
    for (int nf = 0; nf < 4; nf++)
#pragma unroll
        for (int c = 0; c < 4; c++) acc[nf][c] = 0.f;

    const int wm = w & 1, wn = w >> 1;
    {
        const uint32_t xv = (lane & 7) << 4;
        const uint32_t aRowOff = (uint32_t)(wm * 16 + (lane & 7) + ((lane >> 3) & 1) * 8) * 128;
        const uint32_t akbo    = ((lane >> 4) & 1) * 16;
        // paired B x4: lanes 0-15 -> n-frag 2p (k lo/hi), 16-31 -> n-frag 2p+1
        const uint32_t bRow4   = (uint32_t)(wn * 32 + ((lane >> 4) & 1) * 8 + (lane & 7)) * 128;
        const uint32_t bkb4    = ((lane >> 3) & 1) * 16;
#pragma unroll
        for (int kf = 0; kf < 4; kf++) {
            const uint32_t kb = kf * 32;
            uint32_t a4[4];
            ldsm_x4(a4[0], a4[1], a4[2], a4[3], r1b + aRowOff + ((kb + akbo) ^ xv));
#pragma unroll
            for (int p = 0; p < 2; p++) {
                uint32_t bfr[4];
                ldsm_x4(bfr[0], bfr[1], bfr[2], bfr[3],
                        Bsb + bRow4 + p * 2048 + ((kb + bkb4) ^ xv));
                mma16816(acc[2 * p],     a4, bfr);
                mma16816(acc[2 * p + 1], a4, bfr + 2);
            }
        }
    }
    __syncthreads();       // h32 reads done; safe to write tT

    // C frags -> f16 transpose tile tT[o][r] (stride 40)
    {
        const int r_lo = wm * 16 + (lane >> 2);
        const int r_hi = r_lo + 8;
#pragma unroll
        for (int nf = 0; nf < 4; nf++) {
            const int c0 = wn * 32 + nf * 8 + 2 * (lane & 3);
            tT[(c0 + 0) * 40 + r_lo] = __float2half_rn(acc[nf][0]);
            tT[(c0 + 1) * 40 + r_lo] = __float2half_rn(acc[nf][1]);
            tT[(c0 + 0) * 40 + r_hi] = __float2half_rn(acc[nf][2]);
            tT[(c0 + 1) * 40 + r_hi] = __float2half_rn(acc[nf][3]);
        }
    }
    __syncthreads();

    // write WhT: thread -> o = t>>1, r half = (t&1)*16, 2 x uint4
    {
        const int b  = row0 / Nn;
        const int i0 = row0 % Nn;
        const int o  = t >> 1;
        const int rp = (t & 1) * 16;
        __half* dst = g_WhT + ((size_t)b * Ff + o) * Nn + i0 + rp;
        *(uint4*)(dst)     = *(const uint4*)&tT[o * 40 + rp];
        *(uint4*)(dst + 8) = *(const uint4*)&tT[o * 40 + rp + 8];
    }
}

// ---------------------------------------------------------------------------
// Kernel 2: fused GAT via HMMA (R12 structure, B loads via paired ldsm.x4).
// ---------------------------------------------------------------------------
__global__ __launch_bounds__(256, 2) void gat_hmma(float* __restrict__ out)
{
    __shared__ __align__(128) __half A_s[2][MTILE * 64];   // 2 x 8 KB
    __shared__ __align__(128) __half B_s[2][64 * 64];      // 2 x 8 KB
    __shared__ float e1_s[MTILE], E1p_s[MTILE], E1n_s[MTILE];
    __shared__ float Z_s[MTILE];

    const int t    = threadIdx.x;
    const int lane = t & 31;
    const int wid  = t >> 5;      // 0..7
    const int wm   = wid & 3;     // rows wm*16 .. +15
    const int wn   = wid >> 2;    // cols wn*32 .. +31
    const int i0   = blockIdx.x * MTILE;
    const int b    = blockIdx.y;

    if (t < MTILE) {
        float4 p = g_e1pack[(size_t)b * Nn + i0 + t];
        e1_s[t] = p.x; E1p_s[t] = p.y; E1n_s[t] = p.z;
    }
    __syncthreads();

    const uint32_t Abase = smem_u32(A_s);
    const uint32_t Bbase = smem_u32(B_s);

    const uint32_t xv = (lane & 7) << 4;
    const uint32_t aRowOff = (uint32_t)(wm * 16 + (lane & 7) + ((lane >> 3) & 1) * 8) * 128;
    const uint32_t akbo    = ((lane >> 4) & 1) * 16;
    // paired B x4
    const uint32_t bRow4   = (uint32_t)(wn * 32 + ((lane >> 4) & 1) * 8 + (lane & 7)) * 128;
    const uint32_t bkb4    = ((lane >> 3) & 1) * 16;

    const __half* whtB = g_WhT + (size_t)b * Ff * Nn;
    const float4* e2p  = g_e2pack + (size_t)b * Nn;

    const int bf1 = t >> 3, bc1 = t & 7;
    const int bf2 = (t + 256) >> 3;
    const uint32_t bDst1 = Bbase + swz128((uint32_t)(bf1 * 128 + bc1 * 16));
    const uint32_t bDst2 = Bbase + swz128((uint32_t)(bf2 * 128 + bc1 * 16));
    const __half* bSrc1 = whtB + (size_t)bf1 * Nn + bc1 * 8;
    const __half* bSrc2 = whtB + (size_t)bf2 * Nn + bc1 * 8;

#define CPB(S, BUF) do {                                  \
        cp16(bDst1 + (BUF) * 8192, bSrc1 + (S) * JT);     \
        cp16(bDst2 + (BUF) * 8192, bSrc2 + (S) * JT);     \
        CP_COMMIT();                                      \
    } while (0)

    float acc[4][4];
#pragma unroll
    for (int nf = 0; nf < 4; nf++)
#pragma unroll
        for (int c = 0; c < 4; c++) acc[nf][c] = 0.f;

    float zpart[8];
#pragma unroll
    for (int g = 0; g < 8; g++) zpart[g] = 0.f;

#define LOAD_SET(S, JP0, JP1, MM) do {                                           \
        JP0 = __ldg(&e2p[(S) * JT + 2 * lane]);                                  \
        JP1 = __ldg(&e2p[(S) * JT + 2 * lane + 1]);                              \
        _Pragma("unroll")                                                        \
        for (int g = 0; g < 8; g++)                                              \
            MM[g] = __ldg(&g_adjmask[(size_t)(i0 + wid * 8 + g) * (Nn / 64) + (S)]); \
    } while (0)

#define PGEN_C(JP0, JP1, MM, BUF) do {                                           \
        _Pragma("unroll")                                                        \
        for (int g = 0; g < 8; g++) {                                            \
            int i = wid * 8 + g;                                                 \
            float e1v = e1_s[i], e1pv = E1p_s[i], e1nv = E1n_s[i];               \
            float p0 = (e1v + JP0.x > 0.f) ? e1pv * JP0.y : e1nv * JP0.z;        \
            float p1 = (e1v + JP1.x > 0.f) ? e1pv * JP1.y : e1nv * JP1.z;        \
            p0 = ((MM[g] >> (2 * lane)) & 1ull)     ? p0 : 0.f;                  \
            p1 = ((MM[g] >> (2 * lane + 1)) & 1ull) ? p1 : 0.f;                  \
            __half2 ph = __floats2half2_rn(p0, p1);                              \
            float2 pf = __half22float2(ph);                                      \
            zpart[g] += pf.x + pf.y;                                             \
            *(__half2*)((char*)A_s + (BUF) * 8192 +                              \
                        swz128((uint32_t)(i * 128 + lane * 4))) = ph;            \
        }                                                                        \
    } while (0)

#define HMMA(BUF) do {                                                           \
        const uint32_t Ab_ = Abase + (BUF) * 8192;                               \
        const uint32_t Bb_ = Bbase + (BUF) * 8192;                               \
        _Pragma("unroll")                                                        \
        for (int kf = 0; kf < 4; kf++) {                                         \
            const uint32_t kb = kf * 32;                                         \
            uint32_t a4[4];                                                      \
            ldsm_x4(a4[0], a4[1], a4[2], a4[3], Ab_ + aRowOff + ((kb + akbo) ^ xv)); \
            _Pragma("unroll")                                                    \
            for (int p = 0; p < 2; p++) {                                        \
                uint32_t bfr[4];                                                 \
                ldsm_x4(bfr[0], bfr[1], bfr[2], bfr[3],                          \
                        Bb_ + bRow4 + p * 2048 + ((kb + bkb4) ^ xv));            \
                mma16816(acc[2 * p],     a4, bfr);                               \
                mma16816(acc[2 * p + 1], a4, bfr + 2);                           \
            }                                                                    \
        }                                                                        \
    } while (0)

    float4 jpA0, jpA1, jpB0, jpB1;
    ull mA[8], mB[8];

    CPB(0, 0);
    LOAD_SET(0, jpA0, jpA1, mA);
    PGEN_C(jpA0, jpA1, mA, 0);
    LOAD_SET(1, jpB0, jpB1, mB);

#pragma unroll 1
    for (int s = 0; s < NSTEPS; s += 2) {
        CP_WAIT0();
        __syncthreads();
        CPB(s + 1, 1);
        PGEN_C(jpB0, jpB1, mB, 1);
        if (s + 2 < NSTEPS) LOAD_SET(s + 2, jpA0, jpA1, mA);
        HMMA(0);

        CP_WAIT0();
        __syncthreads();
        if (s + 2 < NSTEPS) {
            CPB(s + 2, 0);
            PGEN_C(jpA0, jpA1, mA, 0);
            if (s + 3 < NSTEPS) LOAD_SET(s + 3, jpB0, jpB1, mB);
        }
        HMMA(1);
    }
#undef CPB
#undef LOAD_SET
#undef PGEN_C
#undef HMMA

#pragma unroll
    for (int g = 0; g < 8; g++) {
        float z = zpart[g];
#pragma unroll
        for (int off = 16; off; off >>= 1)
            z += __shfl_xor_sync(0xffffffffu, z, off);
        if (lane == 0) Z_s[wid * 8 + g] = z;
    }
    __syncthreads();

    {
        const int r_lo = wm * 16 + (lane >> 2);
        const int r_hi = r_lo + 8;
        const float zlo = 1.0f / Z_s[r_lo];
        const float zhi = 1.0f / Z_s[r_hi];
        float* olo = out + ((size_t)b * Nn + i0 + r_lo) * 64;
        float* ohi = out + ((size_t)b * Nn + i0 + r_hi) * 64;
#pragma unroll
        for (int nf = 0; nf < 4; nf++) {
            const int col = wn * 32 + nf * 8 + 2 * (lane & 3);
            float2 v;
            v.x = acc[nf][0] * zlo; v.y = acc[nf][1] * zlo;
            v.x = v.x > 0.f ? v.x : expm1f(v.x);
            v.y = v.y > 0.f ? v.y : expm1f(v.y);
            *(float2*)(olo + col) = v;
            v.x = acc[nf][2] * zhi; v.y = acc[nf][3] * zhi;
            v.x = v.x > 0.f ? v.x : expm1f(v.x);
            v.y = v.y > 0.f ? v.y : expm1f(v.y);
            *(float2*)(ohi + col) = v;
        }
    }
}

// ---------------------------------------------------------------------------
extern "C" void kernel_launch(void* const* d_in, const int* in_sizes, int n_in,
                              void* d_out, int out_size)
{
    const float* h = nullptr; const float* adj = nullptr;
    const float* W = nullptr; const float* a = nullptr;
    for (int i = 0; i < n_in; i++) {
        switch (in_sizes[i]) {
            case Bb * Nn * Ff: h   = (const float*)d_in[i]; break;
            case Nn * Nn:      adj = (const float*)d_in[i]; break;
            case Ff * Ff:      W   = (const float*)d_in[i]; break;
            case 2 * Ff:       a   = (const float*)d_in[i]; break;
            default: break;
        }
    }
    (void)out_size;

    prep_pack_kernel<<<PREP_CTAS + PACK_CTAS, 128>>>(h, W, a, adj);
    gat_hmma<<<dim3(Nn / MTILE, Bb), 256>>>((float*)d_out);
}